// round 15
// baseline (speedup 1.0000x reference)
#include <cuda_runtime.h>
#include <cuda_fp16.h>
#include <math.h>

#define DIMV 2048
#define NTR  4096
#define MDEVR 8192
#define TST  500
#define ETA  0.1f
#define NTHREADS 512
#define NWARPS 16
#define RING 32

#define S_DEV_F    4.294967296e9f     /* 2^32 */
#define INV_SDEV   2.3283064365e-10f  /* 2^-32 */

// Persistent device state (static allocation — no cudaMalloc anywhere).
// Barrier counters are never reset (always left at a multiple of nb).
__device__ float              g_gradaccf[DIMV];       // f32 running totals
__device__ unsigned long long g_devstep[TST + 1];     // per-step dev sums
__device__ unsigned           g_arrive_tr;            // train barrier ticket
__device__ unsigned           g_arrive_all;           // full barrier ticket
__device__ unsigned           g_tpub;                 // published snapshots
__device__ unsigned           g_devdone_at[TST + 1];  // dev CTAs done at step
__device__ signed char        g_thring[RING][DIMV];   // int8 theta snapshots
__device__ float              g_sthring[RING];        // their scales
__device__ __half       g_xn_h[(size_t)NTR * DIMV];      // 16.8 MB fp16 train
__device__ signed char  g_dxn_q[(size_t)MDEVR * DIMV];   // 16.8 MB int8 dev
__device__ float        g_sx[MDEVR];                     // per-row dev scales

__device__ __forceinline__ void grid_barrier_full(unsigned nb) {
    __syncthreads();
    if (threadIdx.x == 0) {
        __threadfence();
        unsigned old = atomicAdd(&g_arrive_all, 1u);
        unsigned target = (old / nb + 1u) * nb;
        while (*((volatile unsigned*)&g_arrive_all) < target) { }
        __threadfence();
    }
    __syncthreads();
}

__device__ __forceinline__ float dev_loss_elem(float z, float y) {
    return fmaxf(z, 0.0f) - y * z + log1pf(expf(-fabsf(z)));
}

__device__ __forceinline__ void dot8h(__half2* acc2, const uint4& u, const uint4& th) {
    const __half2* h = (const __half2*)&u;
    const __half2* t = (const __half2*)&th;
    acc2[0] = __hfma2(h[0], t[0], acc2[0]);
    acc2[1] = __hfma2(h[1], t[1], acc2[1]);
    acc2[2] = __hfma2(h[2], t[2], acc2[2]);
    acc2[3] = __hfma2(h[3], t[3], acc2[3]);
}

__device__ __forceinline__ void grad8h(__half2* gj, const uint4& u, __half2 ch2) {
    const __half2* h = (const __half2*)&u;
    gj[0] = __hfma2(ch2, h[0], gj[0]);
    gj[1] = __hfma2(ch2, h[1], gj[1]);
    gj[2] = __hfma2(ch2, h[2], gj[2]);
    gj[3] = __hfma2(ch2, h[3], gj[3]);
}

__device__ __forceinline__ float acc4_to_float(const __half2* a) {
    float2 f0 = __half22float2(a[0]);
    float2 f1 = __half22float2(a[1]);
    float2 f2 = __half22float2(a[2]);
    float2 f3 = __half22float2(a[3]);
    return (f0.x + f0.y) + (f1.x + f1.y) + (f2.x + f2.y) + (f3.x + f3.y);
}

template<int R>
__device__ __forceinline__ void train_chunk(
    int n0, int lane, int t, const __half* s_th, __half2* hacc,
    const float* __restrict__ yn, const float* __restrict__ alphas)
{
    const uint4* xp[R];
#pragma unroll
    for (int r = 0; r < R; r++)
        xp[r] = (const uint4*)(g_xn_h + (size_t)(n0 + r) * DIMV);
    const uint4* tp = (const uint4*)s_th;
    const __half2 hz = __float2half2_rn(0.0f);
    __half2 a[R][4];
#pragma unroll
    for (int r = 0; r < R; r++) { a[r][0]=hz; a[r][1]=hz; a[r][2]=hz; a[r][3]=hz; }
#pragma unroll
    for (int j = 0; j < 8; j++) {
        uint4 th = tp[j*32+lane];
#pragma unroll
        for (int r = 0; r < R; r++) {
            uint4 u = xp[r][j*32+lane];
            dot8h(a[r], u, th);
        }
    }
    float z[R];
#pragma unroll
    for (int r = 0; r < R; r++) z[r] = acc4_to_float(a[r]);
#pragma unroll
    for (int o = 16; o; o >>= 1) {
#pragma unroll
        for (int r = 0; r < R; r++)
            z[r] += __shfl_xor_sync(0xffffffffu, z[r], o);
    }
    __half2 ch[R];
#pragma unroll
    for (int r = 0; r < R; r++) {
        float s = 1.0f / (1.0f + expf(-z[r]));
        float c = alphas[(size_t)t * NTR + (n0 + r)] * (s - yn[n0 + r]);
        ch[r] = __float2half2_rn(c);
    }
#pragma unroll
    for (int j = 0; j < 8; j++) {
#pragma unroll
        for (int r = 0; r < R; r++) {
            uint4 u = xp[r][j*32+lane];         // L1 hits
            grad8h(hacc + j*4, u, ch[r]);
        }
    }
}

template<int R>
__device__ __forceinline__ float dev_chunk_q(
    int m0, int lane, const signed char* s_thq, float sth,
    const float* __restrict__ dyn)
{
    const uint4* xp[R];
#pragma unroll
    for (int r = 0; r < R; r++)
        xp[r] = (const uint4*)(g_dxn_q + (size_t)(m0 + r) * DIMV);
    const uint4* tp = (const uint4*)s_thq;
    int acc[R];
#pragma unroll
    for (int r = 0; r < R; r++) acc[r] = 0;
#pragma unroll
    for (int j = 0; j < 4; j++) {
        uint4 tq = tp[j*32+lane];
#pragma unroll
        for (int r = 0; r < R; r++) {
            uint4 u = xp[r][j*32+lane];
            acc[r] = __dp4a((int)u.x, (int)tq.x, acc[r]);
            acc[r] = __dp4a((int)u.y, (int)tq.y, acc[r]);
            acc[r] = __dp4a((int)u.z, (int)tq.z, acc[r]);
            acc[r] = __dp4a((int)u.w, (int)tq.w, acc[r]);
        }
    }
#pragma unroll
    for (int o = 16; o; o >>= 1) {
#pragma unroll
        for (int r = 0; r < R; r++)
            acc[r] += __shfl_xor_sync(0xffffffffu, acc[r], o);
    }
    float s = 0.0f;
#pragma unroll
    for (int r = 0; r < R; r++) {
        float z = g_sx[m0 + r] * sth * (float)acc[r];
        s += dev_loss_elem(z, dyn[m0 + r]);
    }
    return s;
}

__device__ __forceinline__ signed char quant8(float v, float inv) {
    float q = fminf(fmaxf(v * inv, -127.0f), 127.0f);
    return (signed char)__float2int_rn(q);
}

// ---------------------------------------------------------------------------
__global__ void __launch_bounds__(NTHREADS, 1)
ak_all(const float* __restrict__ theta0,
       const float* __restrict__ xn,  const float* __restrict__ dxn,
       const float* __restrict__ yn,  const float* __restrict__ dyn,
       const float* __restrict__ alphas,
       float* __restrict__ out, int out_size) {
    extern __shared__ char smc[];
    __half*      s_th2h = (__half*)smc;                          // 4 KB fp16
    signed char* s_thq  = (signed char*)(smc + DIMV * 2);        // 2 KB int8
    __half*      s_grad = (__half*)(smc + DIMV * 2 + DIMV);      // 64 KB
    float*       s_dev  = (float*)(smc + DIMV * 2 + DIMV
                                   + (size_t)NWARPS * DIMV * 2); // 16 floats
    float*       s_max  = s_dev + NWARPS;                        // 16 floats
    float*       s_sth  = s_max + NWARPS;                        // 1 float

    const int tid  = threadIdx.x;
    const int lane = tid & 31;
    const int w    = tid >> 5;
    const int cta  = blockIdx.x;
    const int ncta = gridDim.x;
    int C_T = (ncta * 5) >> 3;             // ~62.5% train CTAs
    if (C_T < 1) C_T = 1;
    if (C_T >= ncta) C_T = ncta - 1;
    const int C_D = ncta - C_T;

    // ---------------- phase 0: convert train fp16 + quantize dev int8 ----
    {
        const size_t stride = (size_t)ncta * NTHREADS;
        const size_t gid    = (size_t)cta * NTHREADS + tid;
        const size_t n4 = (size_t)NTR * DIMV / 4;
        const float4* s0 = (const float4*)xn;
        __half2* d0 = (__half2*)g_xn_h;
        for (size_t i = gid; i < n4; i += stride) {
            float4 v = s0[i];
            d0[2*i+0] = __floats2half2_rn(v.x, v.y);
            d0[2*i+1] = __floats2half2_rn(v.z, v.w);
        }
        const int gwp = cta * NWARPS + w;
        const int nwp = ncta * NWARPS;
        for (int row = gwp; row < MDEVR; row += nwp) {
            const float4* xr = (const float4*)(dxn + (size_t)row * DIMV);
            float mx = 0.0f;
            for (int i = lane; i < DIMV / 4; i += 32) {
                float4 v = xr[i];
                mx = fmaxf(mx, fmaxf(fmaxf(fabsf(v.x), fabsf(v.y)),
                                     fmaxf(fabsf(v.z), fabsf(v.w))));
            }
#pragma unroll
            for (int o = 16; o; o >>= 1)
                mx = fmaxf(mx, __shfl_xor_sync(0xffffffffu, mx, o));
            float inv = (mx > 0.0f) ? 127.0f / mx : 0.0f;
            if (lane == 0) g_sx[row] = (mx > 0.0f) ? mx * (1.0f / 127.0f) : 0.0f;
            char4* dq = (char4*)(g_dxn_q + (size_t)row * DIMV);
            for (int i = lane; i < DIMV / 4; i += 32) {
                float4 v = xr[i];
                char4 q;
                q.x = quant8(v.x, inv); q.y = quant8(v.y, inv);
                q.z = quant8(v.z, inv); q.w = quant8(v.w, inv);
                dq[i] = q;
            }
        }
        if (gid < DIMV)      g_gradaccf[gid] = 0.0f;
        if (gid < TST + 1) { g_devstep[gid] = 0ull; g_devdone_at[gid] = 0u; }
        if (gid == 0)        g_tpub = 0u;
        for (size_t j = TST + 1 + gid; j < (size_t)out_size; j += stride)
            out[j] = 0.0f;
    }
    // theta fp32 -> registers (dims 4*tid..+3); publish fp16 + warp max
    float4 thf = ((const float4*)theta0)[tid];
    {
        __half2 h0 = __floats2half2_rn(thf.x, thf.y);
        __half2 h1 = __floats2half2_rn(thf.z, thf.w);
        uint2 u; u.x = *(unsigned*)&h0; u.y = *(unsigned*)&h1;
        ((uint2*)s_th2h)[tid] = u;
        float lm = fmaxf(fmaxf(fabsf(thf.x), fabsf(thf.y)),
                         fmaxf(fabsf(thf.z), fabsf(thf.w)));
#pragma unroll
        for (int o = 16; o; o >>= 1)
            lm = fmaxf(lm, __shfl_xor_sync(0xffffffffu, lm, o));
        if (lane == 0) s_max[w] = lm;
    }
    grid_barrier_full((unsigned)ncta);

    if (cta < C_T) {
        // =================== TRAIN ROLE (sequential chain) ================
        // initial int8 theta publish (cta 0 only)
        if (cta == 0) {
            float gmax = s_max[0];
#pragma unroll
            for (int i = 1; i < NWARPS; i++) gmax = fmaxf(gmax, s_max[i]);
            gmax *= 1.25f;
            float tinv = (gmax > 0.0f) ? 127.0f / gmax : 0.0f;
            char4 tq;
            tq.x = quant8(thf.x, tinv); tq.y = quant8(thf.y, tinv);
            tq.z = quant8(thf.z, tinv); tq.w = quant8(thf.w, tinv);
            ((char4*)g_thring[0])[tid] = tq;
            if (tid == 0) g_sthring[0] = gmax * (1.0f / 127.0f);
            asm volatile("membar.gl;" ::: "memory");
            __syncthreads();
            if (tid == 0) atomicAdd(&g_tpub, 1u);
        }

        const int rb = (int)(((long long)cta * NTR) / C_T);
        const int re = (int)(((long long)(cta + 1) * NTR) / C_T);
        const int Tr = re - rb;
        const int twb = rb + (int)(((long long)Tr * w) / NWARPS);
        const int twe = rb + (int)(((long long)Tr * (w + 1)) / NWARPS);

        float4 prev = make_float4(0.0f, 0.0f, 0.0f, 0.0f);
        const __half2 hz = __float2half2_rn(0.0f);
        unsigned my_arr = 0;

        for (int t = 0; t < TST; ++t) {
            // ---- train rows with theta_t
            __half2 hacc[32];
#pragma unroll
            for (int j = 0; j < 32; j++) hacc[j] = hz;
            {
                int n = twb;
                for (; n + 2 <= twe; n += 2) train_chunk<2>(n, lane, t, s_th2h, hacc, yn, alphas);
                if (n < twe)                 train_chunk<1>(n, lane, t, s_th2h, hacc, yn, alphas);
            }
            {
                uint4* gp4 = (uint4*)(s_grad + (size_t)w * DIMV);
#pragma unroll
                for (int j = 0; j < 8; j++) {
                    uint4 u;
                    ((__half2*)&u)[0] = hacc[j*4+0];
                    ((__half2*)&u)[1] = hacc[j*4+1];
                    ((__half2*)&u)[2] = hacc[j*4+2];
                    ((__half2*)&u)[3] = hacc[j*4+3];
                    gp4[j*32+lane] = u;
                }
            }
            __syncthreads();                              // A

            // ---- CTA reduce + f32 REDs, release, arrive, wait
            {
                const __half2* sg2 = (const __half2*)s_grad;
#pragma unroll
                for (int i = 0; i < 2; i++) {
                    int idx = tid + i * NTHREADS;
                    float2 s = make_float2(0.0f, 0.0f);
#pragma unroll
                    for (int ww = 0; ww < NWARPS; ww++) {
                        float2 f = __half22float2(sg2[ww * (DIMV/2) + idx]);
                        s.x += f.x; s.y += f.y;
                    }
                    atomicAdd(&g_gradaccf[2*idx+0], s.x);
                    atomicAdd(&g_gradaccf[2*idx+1], s.y);
                }
            }
            asm volatile("membar.gl;" ::: "memory");
            __syncthreads();                              // B
            if (tid == 0) {
                my_arr = atomicAdd(&g_arrive_tr, 1u);
                unsigned target = (my_arr / (unsigned)C_T + 1u) * (unsigned)C_T;
                while (*((volatile unsigned*)&g_arrive_tr) < target) { }
            }
            __syncthreads();                              // C

            // ---- update theta regs; publish fp16 smem; cta0 publishes ring
            {
                float4 v = __ldcg(((const float4*)g_gradaccf) + tid);
                thf.x -= ETA * (v.x - prev.x);
                thf.y -= ETA * (v.y - prev.y);
                thf.z -= ETA * (v.z - prev.z);
                thf.w -= ETA * (v.w - prev.w);
                prev = v;
                __half2 h0 = __floats2half2_rn(thf.x, thf.y);
                __half2 h1 = __floats2half2_rn(thf.z, thf.w);
                uint2 u; u.x = *(unsigned*)&h0; u.y = *(unsigned*)&h1;
                ((uint2*)s_th2h)[tid] = u;
            }
            if (cta == 0) {
                // lazy scale from pre-update max, 1.25 margin covers growth
                float gmax = s_max[0];
#pragma unroll
                for (int i = 1; i < NWARPS; i++) gmax = fmaxf(gmax, s_max[i]);
                gmax *= 1.25f;
                float tinv = (gmax > 0.0f) ? 127.0f / gmax : 0.0f;
                char4 tq;
                tq.x = quant8(thf.x, tinv); tq.y = quant8(thf.y, tinv);
                tq.z = quant8(thf.z, tinv); tq.w = quant8(thf.w, tinv);
                // ring backpressure (slot reuse only after dev drained it)
                if (tid == 0 && t + 1 >= RING) {
                    unsigned need = (unsigned)C_D;
                    while (*((volatile unsigned*)&g_devdone_at[t + 1 - RING]) < need) { }
                }
                __syncthreads();                          // cta0-only gate
                ((char4*)g_thring[(t + 1) % RING])[tid] = tq;
                if (tid == 0) g_sthring[(t + 1) % RING] = gmax * (1.0f / 127.0f);
                asm volatile("membar.gl;" ::: "memory");
            }
            // refresh per-warp max of new theta (for next publish scale)
            {
                float lm = fmaxf(fmaxf(fabsf(thf.x), fabsf(thf.y)),
                                 fmaxf(fabsf(thf.z), fabsf(thf.w)));
#pragma unroll
                for (int o = 16; o; o >>= 1)
                    lm = fmaxf(lm, __shfl_xor_sync(0xffffffffu, lm, o));
                __syncthreads();                          // D
                if (lane == 0) s_max[w] = lm;
            }
            __syncthreads();                              // E
            if (cta == 0 && tid == 0) atomicAdd(&g_tpub, 1u);
        }
    } else {
        // =================== DEV ROLE (pipelined consumer) ================
        const int dcta = cta - C_T;
        const int mb = (int)(((long long)dcta * MDEVR) / C_D);
        const int me = (int)(((long long)(dcta + 1) * MDEVR) / C_D);
        const int Dr = me - mb;
        const int dwb = mb + (int)(((long long)Dr * w) / NWARPS);
        const int dwe = mb + (int)(((long long)Dr * (w + 1)) / NWARPS);

        for (int t = 0; t <= TST; ++t) {
            if (tid == 0) {
                while (*((volatile unsigned*)&g_tpub) <= (unsigned)t) { }
            }
            __syncthreads();
            // copy snapshot into smem (L2-direct)
            {
                char4 c = __ldcg(((const char4*)g_thring[t % RING]) + tid);
                ((char4*)s_thq)[tid] = c;
                if (tid == 0) s_sth[0] = __ldcg(&g_sthring[t % RING]);
            }
            __syncthreads();
            float sth = s_sth[0];

            float dsum = 0.0f;
            {
                int m = dwb;
                for (; m + 2 <= dwe; m += 2) dsum += dev_chunk_q<2>(m, lane, s_thq, sth, dyn);
                if (m < dwe)                 dsum += dev_chunk_q<1>(m, lane, s_thq, sth, dyn);
            }
            if (lane == 0) s_dev[w] = dsum;
            __syncthreads();
            if (tid == 0) {
                float s = 0.0f;
#pragma unroll
                for (int i = 0; i < NWARPS; i++) s += s_dev[i];
                atomicAdd(&g_devstep[t], (unsigned long long)llrintf(s * S_DEV_F));
                atomicAdd(&g_devdone_at[t], 1u);   // releases ring slot t
            }
        }
    }

    // ---------------- epilogue: converge, then publish outputs -----------
    grid_barrier_full((unsigned)ncta);
    if (cta == 0) {
        for (int ts = tid; ts < TST; ts += NTHREADS) {
            float L = (float)((long long)g_devstep[ts]) * INV_SDEV * (1.0f / MDEVR);
            if (1 + ts < out_size) out[1 + ts] = L;
        }
        if (tid == 0) {
            float isum = 0.0f;
            for (int ts = 1; ts <= TST; ts++)
                isum += (float)((long long)g_devstep[ts]) * INV_SDEV * (1.0f / MDEVR);
            if (out_size > 0) out[0] = isum / (float)TST;
        }
    }
}

// ---------------------------------------------------------------------------
extern "C" void kernel_launch(void* const* d_in, const int* in_sizes, int n_in,
                              void* d_out, int out_size) {
    const float *theta = nullptr, *alphas = nullptr, *xn = nullptr,
                *yn = nullptr, *dxn = nullptr, *dyn = nullptr;
    for (int i = 0; i < n_in; i++) {
        switch (in_sizes[i]) {
            case DIMV:         theta  = (const float*)d_in[i]; break;
            case TST * NTR:    alphas = (const float*)d_in[i]; break;
            case NTR * DIMV:   xn     = (const float*)d_in[i]; break;
            case NTR:          yn     = (const float*)d_in[i]; break;
            case MDEVR * DIMV: dxn    = (const float*)d_in[i]; break;
            case MDEVR:        dyn    = (const float*)d_in[i]; break;
            default: break;
        }
    }
    float* out = (float*)d_out;

    int dev = 0;
    cudaGetDevice(&dev);
    int nsm = 0;
    cudaDeviceGetAttribute(&nsm, cudaDevAttrMultiProcessorCount, dev);
    int ncta = nsm;
    if (ncta < 2)   ncta = 148;
    if (ncta > 512) ncta = 512;

    size_t smem = (size_t)DIMV * 2            // s_th2h fp16
                + (size_t)DIMV                // s_thq int8
                + (size_t)NWARPS * DIMV * 2   // s_grad
                + (2 * NWARPS + 1) * sizeof(float); // s_dev + s_max + s_sth
    cudaFuncSetAttribute(ak_all, cudaFuncAttributeMaxDynamicSharedMemorySize,
                         (int)smem);

    ak_all<<<ncta, NTHREADS, smem>>>(theta, xn, dxn, yn, dyn, alphas,
                                     out, out_size);
}

// round 16
// speedup vs baseline: 1.0104x; 1.0104x over previous
#include <cuda_runtime.h>
#include <cuda_fp16.h>
#include <math.h>

#define DIMV 2048
#define NTR  4096
#define MDEVR 8192
#define TST  500
#define ETA  0.1f
#define NTHREADS 512
#define NWARPS 16
#define RING 32

#define S_DEV_F    4.294967296e9f     /* 2^32 */
#define INV_SDEV   2.3283064365e-10f  /* 2^-32 */

// Persistent device state (static allocation — no cudaMalloc anywhere).
// Barrier counters are never reset (always left at a multiple of nb).
__device__ float              g_gradaccf[DIMV];       // f32 running totals
__device__ unsigned long long g_devstep[TST + 1];     // per-step dev sums
__device__ unsigned           g_arrive_tr;            // train barrier ticket
__device__ unsigned           g_arrive_all;           // full barrier ticket
__device__ unsigned           g_tpub;                 // published snapshots
__device__ unsigned           g_devdone_at[TST + 1];  // dev CTAs done at step
__device__ signed char        g_thring[RING][DIMV];   // int8 theta snapshots
__device__ float              g_sthring[RING];        // their scales
__device__ __half       g_xn_h[(size_t)NTR * DIMV];      // 16.8 MB fp16 train
__device__ signed char  g_dxn_q[(size_t)MDEVR * DIMV];   // 16.8 MB int8 dev
__device__ float        g_sx[MDEVR];                     // per-row dev scales

__device__ __forceinline__ void grid_barrier_full(unsigned nb) {
    __syncthreads();
    if (threadIdx.x == 0) {
        __threadfence();
        unsigned old = atomicAdd(&g_arrive_all, 1u);
        unsigned target = (old / nb + 1u) * nb;
        while (*((volatile unsigned*)&g_arrive_all) < target) { }
        __threadfence();
    }
    __syncthreads();
}

__device__ __forceinline__ float dev_loss_elem(float z, float y) {
    return fmaxf(z, 0.0f) - y * z + log1pf(expf(-fabsf(z)));
}

__device__ __forceinline__ void dot8h(__half2* acc2, const uint4& u, const uint4& th) {
    const __half2* h = (const __half2*)&u;
    const __half2* t = (const __half2*)&th;
    acc2[0] = __hfma2(h[0], t[0], acc2[0]);
    acc2[1] = __hfma2(h[1], t[1], acc2[1]);
    acc2[2] = __hfma2(h[2], t[2], acc2[2]);
    acc2[3] = __hfma2(h[3], t[3], acc2[3]);
}

__device__ __forceinline__ void grad8h(__half2* gj, const uint4& u, __half2 ch2) {
    const __half2* h = (const __half2*)&u;
    gj[0] = __hfma2(ch2, h[0], gj[0]);
    gj[1] = __hfma2(ch2, h[1], gj[1]);
    gj[2] = __hfma2(ch2, h[2], gj[2]);
    gj[3] = __hfma2(ch2, h[3], gj[3]);
}

__device__ __forceinline__ float acc4_to_float(const __half2* a) {
    float2 f0 = __half22float2(a[0]);
    float2 f1 = __half22float2(a[1]);
    float2 f2 = __half22float2(a[2]);
    float2 f3 = __half22float2(a[3]);
    return (f0.x + f0.y) + (f1.x + f1.y) + (f2.x + f2.y) + (f3.x + f3.y);
}

template<int R>
__device__ __forceinline__ void train_chunk(
    int n0, int lane, int t, const __half* s_th, __half2* hacc,
    const float* __restrict__ yn, const float* __restrict__ alphas)
{
    const uint4* xp[R];
#pragma unroll
    for (int r = 0; r < R; r++)
        xp[r] = (const uint4*)(g_xn_h + (size_t)(n0 + r) * DIMV);
    const uint4* tp = (const uint4*)s_th;
    const __half2 hz = __float2half2_rn(0.0f);
    __half2 a[R][4];
#pragma unroll
    for (int r = 0; r < R; r++) { a[r][0]=hz; a[r][1]=hz; a[r][2]=hz; a[r][3]=hz; }
#pragma unroll
    for (int j = 0; j < 8; j++) {
        uint4 th = tp[j*32+lane];
#pragma unroll
        for (int r = 0; r < R; r++) {
            uint4 u = xp[r][j*32+lane];
            dot8h(a[r], u, th);
        }
    }
    float z[R];
#pragma unroll
    for (int r = 0; r < R; r++) z[r] = acc4_to_float(a[r]);
#pragma unroll
    for (int o = 16; o; o >>= 1) {
#pragma unroll
        for (int r = 0; r < R; r++)
            z[r] += __shfl_xor_sync(0xffffffffu, z[r], o);
    }
    __half2 ch[R];
#pragma unroll
    for (int r = 0; r < R; r++) {
        float s = 1.0f / (1.0f + expf(-z[r]));
        float c = alphas[(size_t)t * NTR + (n0 + r)] * (s - yn[n0 + r]);
        ch[r] = __float2half2_rn(c);
    }
#pragma unroll
    for (int j = 0; j < 8; j++) {
#pragma unroll
        for (int r = 0; r < R; r++) {
            uint4 u = xp[r][j*32+lane];         // L1 hits
            grad8h(hacc + j*4, u, ch[r]);
        }
    }
}

template<int R>
__device__ __forceinline__ float dev_chunk_q(
    int m0, int lane, const signed char* s_thq, float sth,
    const float* __restrict__ dyn)
{
    const uint4* xp[R];
#pragma unroll
    for (int r = 0; r < R; r++)
        xp[r] = (const uint4*)(g_dxn_q + (size_t)(m0 + r) * DIMV);
    const uint4* tp = (const uint4*)s_thq;
    int acc[R];
#pragma unroll
    for (int r = 0; r < R; r++) acc[r] = 0;
#pragma unroll
    for (int j = 0; j < 4; j++) {
        uint4 tq = tp[j*32+lane];
#pragma unroll
        for (int r = 0; r < R; r++) {
            uint4 u = xp[r][j*32+lane];
            acc[r] = __dp4a((int)u.x, (int)tq.x, acc[r]);
            acc[r] = __dp4a((int)u.y, (int)tq.y, acc[r]);
            acc[r] = __dp4a((int)u.z, (int)tq.z, acc[r]);
            acc[r] = __dp4a((int)u.w, (int)tq.w, acc[r]);
        }
    }
#pragma unroll
    for (int o = 16; o; o >>= 1) {
#pragma unroll
        for (int r = 0; r < R; r++)
            acc[r] += __shfl_xor_sync(0xffffffffu, acc[r], o);
    }
    float s = 0.0f;
#pragma unroll
    for (int r = 0; r < R; r++) {
        float z = g_sx[m0 + r] * sth * (float)acc[r];
        s += dev_loss_elem(z, dyn[m0 + r]);
    }
    return s;
}

__device__ __forceinline__ signed char quant8(float v, float inv) {
    float q = fminf(fmaxf(v * inv, -127.0f), 127.0f);
    return (signed char)__float2int_rn(q);
}

// ---------------------------------------------------------------------------
__global__ void __launch_bounds__(NTHREADS, 1)
ak_all(const float* __restrict__ theta0,
       const float* __restrict__ xn,  const float* __restrict__ dxn,
       const float* __restrict__ yn,  const float* __restrict__ dyn,
       const float* __restrict__ alphas,
       float* __restrict__ out, int out_size) {
    extern __shared__ char smc[];
    __half*      s_th2h = (__half*)smc;                          // 4 KB fp16
    signed char* s_thq  = (signed char*)(smc + DIMV * 2);        // 2 KB int8
    __half*      s_grad = (__half*)(smc + DIMV * 2 + DIMV);      // 64 KB
    float*       s_dev  = (float*)(smc + DIMV * 2 + DIMV
                                   + (size_t)NWARPS * DIMV * 2); // 16 floats
    float*       s_max  = s_dev + NWARPS;                        // 16 floats
    float*       s_sth  = s_max + NWARPS;                        // 1 float

    const int tid  = threadIdx.x;
    const int lane = tid & 31;
    const int w    = tid >> 5;
    const int cta  = blockIdx.x;
    const int ncta = gridDim.x;
    int C_T = (ncta * 5) >> 3;             // ~62.5% train CTAs
    if (C_T < 1) C_T = 1;
    if (C_T >= ncta) C_T = ncta - 1;
    const int C_D = ncta - C_T;

    // ---------------- phase 0: convert train fp16 + quantize dev int8 ----
    {
        const size_t stride = (size_t)ncta * NTHREADS;
        const size_t gid    = (size_t)cta * NTHREADS + tid;
        const size_t n4 = (size_t)NTR * DIMV / 4;
        const float4* s0 = (const float4*)xn;
        __half2* d0 = (__half2*)g_xn_h;
        for (size_t i = gid; i < n4; i += stride) {
            float4 v = s0[i];
            d0[2*i+0] = __floats2half2_rn(v.x, v.y);
            d0[2*i+1] = __floats2half2_rn(v.z, v.w);
        }
        const int gwp = cta * NWARPS + w;
        const int nwp = ncta * NWARPS;
        for (int row = gwp; row < MDEVR; row += nwp) {
            const float4* xr = (const float4*)(dxn + (size_t)row * DIMV);
            float mx = 0.0f;
            for (int i = lane; i < DIMV / 4; i += 32) {
                float4 v = xr[i];
                mx = fmaxf(mx, fmaxf(fmaxf(fabsf(v.x), fabsf(v.y)),
                                     fmaxf(fabsf(v.z), fabsf(v.w))));
            }
#pragma unroll
            for (int o = 16; o; o >>= 1)
                mx = fmaxf(mx, __shfl_xor_sync(0xffffffffu, mx, o));
            float inv = (mx > 0.0f) ? 127.0f / mx : 0.0f;
            if (lane == 0) g_sx[row] = (mx > 0.0f) ? mx * (1.0f / 127.0f) : 0.0f;
            char4* dq = (char4*)(g_dxn_q + (size_t)row * DIMV);
            for (int i = lane; i < DIMV / 4; i += 32) {
                float4 v = xr[i];
                char4 q;
                q.x = quant8(v.x, inv); q.y = quant8(v.y, inv);
                q.z = quant8(v.z, inv); q.w = quant8(v.w, inv);
                dq[i] = q;
            }
        }
        if (gid < DIMV)      g_gradaccf[gid] = 0.0f;
        if (gid < TST + 1) { g_devstep[gid] = 0ull; g_devdone_at[gid] = 0u; }
        if (gid == 0)        g_tpub = 0u;
        for (size_t j = TST + 1 + gid; j < (size_t)out_size; j += stride)
            out[j] = 0.0f;
    }
    // theta fp32 -> registers (dims 4*tid..+3); publish fp16 + warp max
    float4 thf = ((const float4*)theta0)[tid];
    {
        __half2 h0 = __floats2half2_rn(thf.x, thf.y);
        __half2 h1 = __floats2half2_rn(thf.z, thf.w);
        uint2 u; u.x = *(unsigned*)&h0; u.y = *(unsigned*)&h1;
        ((uint2*)s_th2h)[tid] = u;
        float lm = fmaxf(fmaxf(fabsf(thf.x), fabsf(thf.y)),
                         fmaxf(fabsf(thf.z), fabsf(thf.w)));
#pragma unroll
        for (int o = 16; o; o >>= 1)
            lm = fmaxf(lm, __shfl_xor_sync(0xffffffffu, lm, o));
        if (lane == 0) s_max[w] = lm;
    }
    grid_barrier_full((unsigned)ncta);

    if (cta < C_T) {
        // =================== TRAIN ROLE (sequential chain) ================
        // initial int8 theta publish (cta 0 only)
        if (cta == 0) {
            float gmax = s_max[0];
#pragma unroll
            for (int i = 1; i < NWARPS; i++) gmax = fmaxf(gmax, s_max[i]);
            gmax *= 1.25f;
            float tinv = (gmax > 0.0f) ? 127.0f / gmax : 0.0f;
            char4 tq;
            tq.x = quant8(thf.x, tinv); tq.y = quant8(thf.y, tinv);
            tq.z = quant8(thf.z, tinv); tq.w = quant8(thf.w, tinv);
            ((char4*)g_thring[0])[tid] = tq;
            if (tid == 0) g_sthring[0] = gmax * (1.0f / 127.0f);
            asm volatile("membar.gl;" ::: "memory");
            __syncthreads();
            if (tid == 0) atomicAdd(&g_tpub, 1u);
        }

        const int rb = (int)(((long long)cta * NTR) / C_T);
        const int re = (int)(((long long)(cta + 1) * NTR) / C_T);
        const int Tr = re - rb;
        const int twb = rb + (int)(((long long)Tr * w) / NWARPS);
        const int twe = rb + (int)(((long long)Tr * (w + 1)) / NWARPS);

        float4 prev = make_float4(0.0f, 0.0f, 0.0f, 0.0f);
        const __half2 hz = __float2half2_rn(0.0f);
        unsigned my_arr = 0;

        for (int t = 0; t < TST; ++t) {
            // ---- train rows with theta_t
            __half2 hacc[32];
#pragma unroll
            for (int j = 0; j < 32; j++) hacc[j] = hz;
            {
                int n = twb;
                for (; n + 2 <= twe; n += 2) train_chunk<2>(n, lane, t, s_th2h, hacc, yn, alphas);
                if (n < twe)                 train_chunk<1>(n, lane, t, s_th2h, hacc, yn, alphas);
            }
            {
                uint4* gp4 = (uint4*)(s_grad + (size_t)w * DIMV);
#pragma unroll
                for (int j = 0; j < 8; j++) {
                    uint4 u;
                    ((__half2*)&u)[0] = hacc[j*4+0];
                    ((__half2*)&u)[1] = hacc[j*4+1];
                    ((__half2*)&u)[2] = hacc[j*4+2];
                    ((__half2*)&u)[3] = hacc[j*4+3];
                    gp4[j*32+lane] = u;
                }
            }
            __syncthreads();                              // A

            // ---- CTA reduce + f32 REDs, release, arrive, wait
            {
                const __half2* sg2 = (const __half2*)s_grad;
#pragma unroll
                for (int i = 0; i < 2; i++) {
                    int idx = tid + i * NTHREADS;
                    float2 s = make_float2(0.0f, 0.0f);
#pragma unroll
                    for (int ww = 0; ww < NWARPS; ww++) {
                        float2 f = __half22float2(sg2[ww * (DIMV/2) + idx]);
                        s.x += f.x; s.y += f.y;
                    }
                    atomicAdd(&g_gradaccf[2*idx+0], s.x);
                    atomicAdd(&g_gradaccf[2*idx+1], s.y);
                }
            }
            asm volatile("membar.gl;" ::: "memory");
            __syncthreads();                              // B
            if (tid == 0) {
                my_arr = atomicAdd(&g_arrive_tr, 1u);
                unsigned target = (my_arr / (unsigned)C_T + 1u) * (unsigned)C_T;
                while (*((volatile unsigned*)&g_arrive_tr) < target) { }
            }
            __syncthreads();                              // C

            // ---- update theta regs; publish fp16 smem; cta0 publishes ring
            {
                float4 v = __ldcg(((const float4*)g_gradaccf) + tid);
                thf.x -= ETA * (v.x - prev.x);
                thf.y -= ETA * (v.y - prev.y);
                thf.z -= ETA * (v.z - prev.z);
                thf.w -= ETA * (v.w - prev.w);
                prev = v;
                __half2 h0 = __floats2half2_rn(thf.x, thf.y);
                __half2 h1 = __floats2half2_rn(thf.z, thf.w);
                uint2 u; u.x = *(unsigned*)&h0; u.y = *(unsigned*)&h1;
                ((uint2*)s_th2h)[tid] = u;
            }
            if (cta == 0) {
                // lazy scale from pre-update max, 1.25 margin covers growth
                float gmax = s_max[0];
#pragma unroll
                for (int i = 1; i < NWARPS; i++) gmax = fmaxf(gmax, s_max[i]);
                gmax *= 1.25f;
                float tinv = (gmax > 0.0f) ? 127.0f / gmax : 0.0f;
                char4 tq;
                tq.x = quant8(thf.x, tinv); tq.y = quant8(thf.y, tinv);
                tq.z = quant8(thf.z, tinv); tq.w = quant8(thf.w, tinv);
                // ring backpressure (slot reuse only after dev drained it)
                if (tid == 0 && t + 1 >= RING) {
                    unsigned need = (unsigned)C_D;
                    while (*((volatile unsigned*)&g_devdone_at[t + 1 - RING]) < need) { }
                }
                __syncthreads();                          // cta0-only gate
                ((char4*)g_thring[(t + 1) % RING])[tid] = tq;
                if (tid == 0) g_sthring[(t + 1) % RING] = gmax * (1.0f / 127.0f);
                asm volatile("membar.gl;" ::: "memory");
            }
            // refresh per-warp max of new theta (for next publish scale)
            {
                float lm = fmaxf(fmaxf(fabsf(thf.x), fabsf(thf.y)),
                                 fmaxf(fabsf(thf.z), fabsf(thf.w)));
#pragma unroll
                for (int o = 16; o; o >>= 1)
                    lm = fmaxf(lm, __shfl_xor_sync(0xffffffffu, lm, o));
                __syncthreads();                          // D
                if (lane == 0) s_max[w] = lm;
            }
            __syncthreads();                              // E
            if (cta == 0 && tid == 0) atomicAdd(&g_tpub, 1u);
        }
    } else {
        // =================== DEV ROLE (pipelined consumer) ================
        const int dcta = cta - C_T;
        const int mb = (int)(((long long)dcta * MDEVR) / C_D);
        const int me = (int)(((long long)(dcta + 1) * MDEVR) / C_D);
        const int Dr = me - mb;
        const int dwb = mb + (int)(((long long)Dr * w) / NWARPS);
        const int dwe = mb + (int)(((long long)Dr * (w + 1)) / NWARPS);

        for (int t = 0; t <= TST; ++t) {
            if (tid == 0) {
                while (*((volatile unsigned*)&g_tpub) <= (unsigned)t) { }
            }
            __syncthreads();
            // copy snapshot into smem (L2-direct)
            {
                char4 c = __ldcg(((const char4*)g_thring[t % RING]) + tid);
                ((char4*)s_thq)[tid] = c;
                if (tid == 0) s_sth[0] = __ldcg(&g_sthring[t % RING]);
            }
            __syncthreads();
            float sth = s_sth[0];

            float dsum = 0.0f;
            {
                int m = dwb;
                for (; m + 2 <= dwe; m += 2) dsum += dev_chunk_q<2>(m, lane, s_thq, sth, dyn);
                if (m < dwe)                 dsum += dev_chunk_q<1>(m, lane, s_thq, sth, dyn);
            }
            if (lane == 0) s_dev[w] = dsum;
            __syncthreads();
            if (tid == 0) {
                float s = 0.0f;
#pragma unroll
                for (int i = 0; i < NWARPS; i++) s += s_dev[i];
                atomicAdd(&g_devstep[t], (unsigned long long)llrintf(s * S_DEV_F));
                atomicAdd(&g_devdone_at[t], 1u);   // releases ring slot t
            }
        }
    }

    // ---------------- epilogue: converge, then publish outputs -----------
    grid_barrier_full((unsigned)ncta);
    if (cta == 0) {
        for (int ts = tid; ts < TST; ts += NTHREADS) {
            float L = (float)((long long)g_devstep[ts]) * INV_SDEV * (1.0f / MDEVR);
            if (1 + ts < out_size) out[1 + ts] = L;
        }
        if (tid == 0) {
            float isum = 0.0f;
            for (int ts = 1; ts <= TST; ts++)
                isum += (float)((long long)g_devstep[ts]) * INV_SDEV * (1.0f / MDEVR);
            if (out_size > 0) out[0] = isum / (float)TST;
        }
    }
}

// ---------------------------------------------------------------------------
extern "C" void kernel_launch(void* const* d_in, const int* in_sizes, int n_in,
                              void* d_out, int out_size) {
    const float *theta = nullptr, *alphas = nullptr, *xn = nullptr,
                *yn = nullptr, *dxn = nullptr, *dyn = nullptr;
    for (int i = 0; i < n_in; i++) {
        switch (in_sizes[i]) {
            case DIMV:         theta  = (const float*)d_in[i]; break;
            case TST * NTR:    alphas = (const float*)d_in[i]; break;
            case NTR * DIMV:   xn     = (const float*)d_in[i]; break;
            case NTR:          yn     = (const float*)d_in[i]; break;
            case MDEVR * DIMV: dxn    = (const float*)d_in[i]; break;
            case MDEVR:        dyn    = (const float*)d_in[i]; break;
            default: break;
        }
    }
    float* out = (float*)d_out;

    int dev = 0;
    cudaGetDevice(&dev);
    int nsm = 0;
    cudaDeviceGetAttribute(&nsm, cudaDevAttrMultiProcessorCount, dev);
    int ncta = nsm;
    if (ncta < 2)   ncta = 148;
    if (ncta > 512) ncta = 512;

    size_t smem = (size_t)DIMV * 2            // s_th2h fp16
                + (size_t)DIMV                // s_thq int8
                + (size_t)NWARPS * DIMV * 2   // s_grad
                + (2 * NWARPS + 1) * sizeof(float); // s_dev + s_max + s_sth
    cudaFuncSetAttribute(ak_all, cudaFuncAttributeMaxDynamicSharedMemorySize,
                         (int)smem);

    ak_all<<<ncta, NTHREADS, smem>>>(theta, xn, dxn, yn, dyn, alphas,
                                     out, out_size);
}